// round 16
// baseline (speedup 1.0000x reference)
#include <cuda_runtime.h>
#include <cuda_fp16.h>
#include <math.h>
#include <stdint.h>

// Problem constants
#define BATCH 4096
#define DDIM  512
#define SLOTS 16
#define NROWS (BATCH * SLOTS)   // 65536
#define N3    (3 * DDIM)        // 1536

// ---------------------------------------------------------------------------
// Scratch buffers (device globals — no allocations allowed)
// ---------------------------------------------------------------------------
__device__ float g_QKV [(size_t)NROWS * N3];     // Q|K|V fp32
__device__ float g_KVx [(size_t)BATCH * 1024];   // Kx|Vx fp32
__device__ float g_mlp [(size_t)NROWS * DDIM];   // mlp1 out, then mlp2 out
__device__ float g_xz  [(size_t)BATCH * N3];
__device__ float g_z   [(size_t)NROWS * N3];     // sigmoid(z) from MODE-1 GEMM

// fp16 hi/lo split activations
__device__ __half g_cs_h [(size_t)NROWS * DDIM], g_cs_l [(size_t)NROWS * DDIM];
__device__ __half g_hs_h [(size_t)NROWS * DDIM];
__device__ __half g_in_h [(size_t)BATCH * DDIM], g_in_l [(size_t)BATCH * DDIM];
__device__ __half g_att_h[(size_t)NROWS * DDIM], g_att_l[(size_t)NROWS * DDIM];
__device__ __half g_ln_h [(size_t)NROWS * DDIM], g_ln_l [(size_t)NROWS * DDIM];

// Transposed + split weights: [N][K=512] fp16 hi/lo
__device__ __half g_wqkv_h[N3 * DDIM],  g_wqkv_l[N3 * DDIM];  // rows: Q|K|V
__device__ __half g_m1_h[DDIM * DDIM],  g_m1_l[DDIM * DDIM];
__device__ __half g_m2_h[DDIM * DDIM],  g_m2_l[DDIM * DDIM];
__device__ __half g_kr_h[DDIM * N3];    // gates hi only
__device__ __half g_rk_h[DDIM * N3];

// ---------------------------------------------------------------------------
// Helpers
// ---------------------------------------------------------------------------
__device__ __forceinline__ uint32_t smem_u32(const void* p) {
    uint32_t a;
    asm("{ .reg .u64 t; cvta.to.shared.u64 t, %1; cvt.u32.u64 %0, t; }"
        : "=r"(a) : "l"(p));
    return a;
}
__device__ __forceinline__ uint32_t pack2h(__half a, __half b) {
    return (uint32_t)__half_as_ushort(a) |
           ((uint32_t)__half_as_ushort(b) << 16);
}

#define CP16(dst, src) \
    asm volatile("cp.async.ca.shared.global [%0], [%1], 16;" \
                 :: "r"(dst), "l"(src) : "memory")
#define CP_COMMIT()  asm volatile("cp.async.commit_group;" ::: "memory")
#define CP_WAIT0()   asm volatile("cp.async.wait_group 0;" ::: "memory")

#define LDSM4(r0, r1, r2, r3, addr) \
    asm volatile("ldmatrix.sync.aligned.m8n8.x4.shared.b16 {%0,%1,%2,%3}, [%4];" \
                 : "=r"(r0), "=r"(r1), "=r"(r2), "=r"(r3) : "r"(addr))

#define MMA_F16(ac, a0, a1, a2, a3, b0, b1) \
    asm volatile("mma.sync.aligned.m16n8k16.row.col.f32.f16.f16.f32 " \
                 "{%0,%1,%2,%3},{%4,%5,%6,%7},{%8,%9},{%0,%1,%2,%3};" \
                 : "+f"((ac)[0]), "+f"((ac)[1]), "+f"((ac)[2]), "+f"((ac)[3]) \
                 : "r"(a0), "r"(a1), "r"(a2), "r"(a3), "r"(b0), "r"(b1))

// ---------------------------------------------------------------------------
// Mega prep: weight prep + all three activation splits in ONE launch.
// Block ranges:
//   [0, 11264)          weight prep (as before)
//   [11264, 44032)      c_state split -> hi/lo
//   [44032, 76800)      h_state split -> hi only
//   [76800, 78848)      inputs  split -> hi/lo
// ---------------------------------------------------------------------------
#define PREP_W_BLKS   11264
#define CS_BLKS       32768
#define HS_BLKS       32768
#define IN_BLKS       2048
#define MEGA_BLKS     (PREP_W_BLKS + CS_BLKS + HS_BLKS + IN_BLKS)

__global__ __launch_bounds__(256)
void prep_split_all(const float* __restrict__ Wq, const float* __restrict__ Wk,
                    const float* __restrict__ Wv, const float* __restrict__ M1,
                    const float* __restrict__ M2, const float* __restrict__ Kr,
                    const float* __restrict__ Rk,
                    __half* __restrict__ wqkvh, __half* __restrict__ wqkvl,
                    __half* __restrict__ m1h, __half* __restrict__ m1l,
                    __half* __restrict__ m2h, __half* __restrict__ m2l,
                    __half* __restrict__ krh, __half* __restrict__ rkh,
                    const float* __restrict__ cs, __half* __restrict__ csh,
                    __half* __restrict__ csl,
                    const float* __restrict__ hs, __half* __restrict__ hsh,
                    const float* __restrict__ in, __half* __restrict__ inh,
                    __half* __restrict__ inl)
{
    const int blk = blockIdx.x;
    if (blk < PREP_W_BLKS) {
        if (blk < 5120) {
            int seg = blk >> 10;
            int idx = ((blk & 1023) << 8) + threadIdx.x;
            const float* W; __half* Wh; __half* Wl;
            switch (seg) {
                case 0: W = Wq; Wh = wqkvh;              Wl = wqkvl;              break;
                case 1: W = Wk; Wh = wqkvh + 512 * 512;  Wl = wqkvl + 512 * 512;  break;
                case 2: W = Wv; Wh = wqkvh + 1024 * 512; Wl = wqkvl + 1024 * 512; break;
                case 3: W = M1; Wh = m1h; Wl = m1l; break;
                default:W = M2; Wh = m2h; Wl = m2l; break;
            }
            int k = idx >> 9, n = idx & 511;
            float x = W[idx];
            __half h = __float2half_rn(x);
            Wh[(size_t)n * 512 + k] = h;
            Wl[(size_t)n * 512 + k] = __float2half_rn(x - __half2float(h));
        } else {
            const float* W; __half* Wh; int idx;
            if (blk < 8192) { idx = ((blk - 5120) << 8) + threadIdx.x; W = Kr; Wh = krh; }
            else            { idx = ((blk - 8192) << 8) + threadIdx.x; W = Rk; Wh = rkh; }
            int k = idx / N3, n = idx - k * N3;
            Wh[(size_t)n * 512 + k] = __float2half_rn(W[idx]);
        }
        return;
    }
    // splits (float4 per thread)
    const float* X; __half* H; __half* L; size_t idx;
    if (blk < PREP_W_BLKS + CS_BLKS) {
        idx = (size_t)(blk - PREP_W_BLKS) * 256 + threadIdx.x;
        X = cs; H = csh; L = csl;
    } else if (blk < PREP_W_BLKS + CS_BLKS + HS_BLKS) {
        idx = (size_t)(blk - PREP_W_BLKS - CS_BLKS) * 256 + threadIdx.x;
        X = hs; H = hsh; L = nullptr;
    } else {
        idx = (size_t)(blk - PREP_W_BLKS - CS_BLKS - HS_BLKS) * 256 + threadIdx.x;
        X = in; H = inh; L = inl;
    }
    float4 x = reinterpret_cast<const float4*>(X)[idx];
    __half h0 = __float2half_rn(x.x), h1 = __float2half_rn(x.y);
    __half h2 = __float2half_rn(x.z), h3 = __float2half_rn(x.w);
    reinterpret_cast<uint2*>(H)[idx] = make_uint2(pack2h(h0, h1), pack2h(h2, h3));
    if (L) {
        __half l0 = __float2half_rn(x.x - __half2float(h0));
        __half l1 = __float2half_rn(x.y - __half2float(h1));
        __half l2 = __float2half_rn(x.z - __half2float(h2));
        __half l3 = __float2half_rn(x.w - __half2float(h3));
        reinterpret_cast<uint2*>(L)[idx] = make_uint2(pack2h(l0, l1), pack2h(l2, l3));
    }
}

// ---------------------------------------------------------------------------
// mma.sync fp16-split GEMM: C(M,N) = A(M,512) @ W(512,N)
// NT terms: 3 = AhBh+AlBh+AhBl (QKV), 2 = AhBh+AlBh (mlp), 1 = AhBh (gates).
// CTA 128x128, BK=32, 8 warps, warp tile 64x32, 2-stage cp.async pipeline,
// 2 CTAs/SM. MODE 0: plain store. MODE 1: sigmoid(acc + xz + bias).
// ---------------------------------------------------------------------------
#define TM 128
#define TN 128
#define TK 32
#define NCH 16
#define RSB 80
#define OFF_AH 0
#define OFF_AL (128 * RSB)
#define OFF_BH (256 * RSB)
#define OFF_BL (384 * RSB)
#define STAGE_B (512 * RSB)       // 40960
#define GEMM_SMEM (2 * STAGE_B)   // 81920 -> 2 CTAs/SM

template <int NT, int MODE>
__global__ __launch_bounds__(256, 2)
void tc_gemm(const __half* __restrict__ Ah, const __half* __restrict__ Al,
             const __half* __restrict__ Bh, const __half* __restrict__ Bl,
             float* __restrict__ C, int N,
             const float* __restrict__ xz, const float* __restrict__ bias)
{
    extern __shared__ char smem[];
    const uint32_t tb = smem_u32(smem);

    const int t    = threadIdx.x;
    const int w    = t >> 5;
    const int lane = t & 31;
    const int wmBase = (w >> 2) * 64;
    const int wnBase = (w & 3) * 32;
    const int rowBase = blockIdx.y * TM;
    const int nBase   = blockIdx.x * TN;

    const uint32_t aRow = (uint32_t)(lane & 15);
    const uint32_t aK   = (uint32_t)((lane >> 4) * 8);
    const uint32_t bRow = (uint32_t)((lane & 7) + ((lane >> 4) << 3));
    const uint32_t bK   = (uint32_t)(((lane >> 3) & 1) * 8);

    float acc[4][4][4];
#pragma unroll
    for (int i = 0; i < 4; i++)
#pragma unroll
        for (int j = 0; j < 4; j++)
#pragma unroll
            for (int q = 0; q < 4; q++) acc[i][j][q] = 0.f;

    auto issue = [&](int c, int s) {
        const uint32_t st = tb + s * STAGE_B;
        const int kb = c * TK;
#pragma unroll
        for (int i = 0; i < 2; i++) {
            int v = i * 256 + t;
            int row = v >> 2, seg = v & 3;
            const size_t so = (size_t)(rowBase + row) * 512 + kb + seg * 8;
            uint32_t doff = (uint32_t)(row * RSB + seg * 16);
            CP16(st + OFF_AH + doff, Ah + so);
            if (NT >= 2) CP16(st + OFF_AL + doff, Al + so);
        }
#pragma unroll
        for (int i = 0; i < 2; i++) {
            int v = i * 256 + t;
            int row = v >> 2, seg = v & 3;
            const size_t so = (size_t)(nBase + row) * 512 + kb + seg * 8;
            uint32_t doff = (uint32_t)(row * RSB + seg * 16);
            CP16(st + OFF_BH + doff, Bh + so);
            if (NT == 3) CP16(st + OFF_BL + doff, Bl + so);
        }
        CP_COMMIT();
    };

    auto compute = [&](int s) {
        const uint32_t sAh = tb + s * STAGE_B + OFF_AH;
        const uint32_t sAl = tb + s * STAGE_B + OFF_AL;
        const uint32_t sBh = tb + s * STAGE_B + OFF_BH;
        const uint32_t sBl = tb + s * STAGE_B + OFF_BL;
#pragma unroll
        for (int kk = 0; kk < TK; kk += 16) {
            uint32_t bh[2][4], bl[2][4];
#pragma unroll
            for (int p = 0; p < 2; p++) {
                uint32_t addr = (uint32_t)((wnBase + p * 16 + bRow) * RSB + (kk + bK) * 2);
                LDSM4(bh[p][0], bh[p][1], bh[p][2], bh[p][3], sBh + addr);
                if (NT == 3) LDSM4(bl[p][0], bl[p][1], bl[p][2], bl[p][3], sBl + addr);
            }
#pragma unroll
            for (int mi = 0; mi < 4; mi++) {
                uint32_t addr = (uint32_t)((wmBase + mi * 16 + aRow) * RSB + (kk + aK) * 2);
                uint32_t ah0, ah1, ah2, ah3, al0, al1, al2, al3;
                LDSM4(ah0, ah1, ah2, ah3, sAh + addr);
                if (NT >= 2) LDSM4(al0, al1, al2, al3, sAl + addr);
#pragma unroll
                for (int g = 0; g < 4; g++) {
                    int p = g >> 1, q = (g & 1) * 2;
                    MMA_F16(acc[mi][g], ah0, ah1, ah2, ah3, bh[p][q], bh[p][q + 1]);
                    if (NT >= 2)
                        MMA_F16(acc[mi][g], al0, al1, al2, al3, bh[p][q], bh[p][q + 1]);
                    if (NT == 3)
                        MMA_F16(acc[mi][g], ah0, ah1, ah2, ah3, bl[p][q], bl[p][q + 1]);
                }
            }
        }
    };

    issue(0, 0);
    for (int c = 0; c < NCH; c++) {
        const int s = c & 1;
        CP_WAIT0();
        __syncthreads();
        if (c + 1 < NCH) issue(c + 1, s ^ 1);
        compute(s);
    }

    const int tr  = lane >> 2;
    const int tc2 = (lane & 3) * 2;
#pragma unroll
    for (int mi = 0; mi < 4; mi++) {
#pragma unroll
        for (int g = 0; g < 4; g++) {
            int row = rowBase + wmBase + mi * 16 + tr;
            int col = nBase + wnBase + g * 8 + tc2;
            float v0 = acc[mi][g][0], v1 = acc[mi][g][1];
            float v2 = acc[mi][g][2], v3 = acc[mi][g][3];
            if (MODE == 1) {
                const float* xr0 = xz + (size_t)(row >> 4) * N3 + col;
                const float* xr1 = xz + (size_t)((row + 8) >> 4) * N3 + col;
                float b0 = bias[col], b1 = bias[col + 1];
                v0 = 1.f / (1.f + expf(-(v0 + xr0[0] + b0)));
                v1 = 1.f / (1.f + expf(-(v1 + xr0[1] + b1)));
                v2 = 1.f / (1.f + expf(-(v2 + xr1[0] + b0)));
                v3 = 1.f / (1.f + expf(-(v3 + xr1[1] + b1)));
            }
            *reinterpret_cast<float2*>(C + (size_t)row * N + col)       = make_float2(v0, v1);
            *reinterpret_cast<float2*>(C + (size_t)(row + 8) * N + col) = make_float2(v2, v3);
        }
    }
}

// ---------------------------------------------------------------------------
// Attention: one block per batch, 512 threads (16 warps), full smem staging.
// AV phase uses 16 independent accumulators (same l-order -> bit-identical).
// ---------------------------------------------------------------------------
__global__ __launch_bounds__(512)
void attn_k(const float* __restrict__ QKV, const float* __restrict__ KVx,
            __half* __restrict__ AttH, __half* __restrict__ AttL)
{
    extern __shared__ float sm[];
    float* sQ = sm;                 // 16*512
    float* sK = sQ + 8192;          // 17*512
    float* sV = sK + 8704;          // 17*512
    float* sS = sV + 8704;          // 16*17

    const int b = blockIdx.x;
    const int t = threadIdx.x;
    const size_t base3 = (size_t)b * SLOTS * N3;

    // load Q/K/V rows as float4 (2048 float4 per tensor)
    for (int i = t; i < 2048; i += 512) {
        int j = i >> 7, d4 = i & 127;
        const float4* row = reinterpret_cast<const float4*>(QKV + base3 + (size_t)j * N3);
        reinterpret_cast<float4*>(sQ)[i] = row[d4];
        reinterpret_cast<float4*>(sK)[i] = row[128 + d4];
        reinterpret_cast<float4*>(sV)[i] = row[256 + d4];
    }
    for (int i = t; i < 128; i += 512) {
        const float4* kx = reinterpret_cast<const float4*>(KVx + (size_t)b * 1024);
        reinterpret_cast<float4*>(sK + 8192)[i] = kx[i];
        reinterpret_cast<float4*>(sV + 8192)[i] = kx[128 + i];
    }
    __syncthreads();

    // 272 dots of length 512; 16 warps x 17 each
    const int w = t >> 5, lane = t & 31;
    for (int p = w; p < 272; p += 16) {
        int j = p / 17, l = p - j * 17;
        const float* q = sQ + j * 512;
        const float* k = sK + l * 512;
        float s = 0.f;
        for (int d = lane; d < 512; d += 32) s += q[d] * k[d];
#pragma unroll
        for (int o = 16; o; o >>= 1) s += __shfl_xor_sync(0xffffffffu, s, o);
        if (lane == 0) sS[p] = s * 22.627416997969522f;
    }
    __syncthreads();

    if (t < 16) {
        float m = -INFINITY;
        for (int l = 0; l < 17; l++) m = fmaxf(m, sS[t * 17 + l]);
        float sum = 0.f;
        for (int l = 0; l < 17; l++) {
            float e = expf(sS[t * 17 + l] - m);
            sS[t * 17 + l] = e;
            sum += e;
        }
        float inv = 1.f / sum;
        for (int l = 0; l < 17; l++) sS[t * 17 + l] *= inv;
    }
    __syncthreads();

    // AV: each thread owns column d = t; 16 independent accumulators
    float acc[16];
#pragma unroll
    for (int j = 0; j < 16; j++) acc[j] = 0.f;
#pragma unroll
    for (int l = 0; l < 17; l++) {
        float v = sV[l * 512 + t];
#pragma unroll
        for (int j = 0; j < 16; j++) acc[j] += sS[j * 17 + l] * v;
    }
    const size_t obase = (size_t)b * 8192;
#pragma unroll
    for (int j = 0; j < 16; j++) {
        __half h = __float2half_rn(acc[j]);
        AttH[obase + j * 512 + t] = h;
        AttL[obase + j * 512 + t] = __float2half_rn(acc[j] - __half2float(h));
    }
}

// ---------------------------------------------------------------------------
// LN1 (relu + fp16 hi/lo split output)
// ---------------------------------------------------------------------------
__global__ __launch_bounds__(256)
void ln1_k(const float* __restrict__ X, __half* __restrict__ YH,
           __half* __restrict__ YL, const float* __restrict__ gain,
           const float* __restrict__ bias)
{
    const int row  = blockIdx.x * 8 + (threadIdx.x >> 5);
    const int lane = threadIdx.x & 31;
    const float4* in = reinterpret_cast<const float4*>(X + (size_t)row * 512);

    float4 v[4];
    float sum = 0.f, sq = 0.f;
#pragma unroll
    for (int i = 0; i < 4; i++) {
        v[i] = in[lane + i * 32];
        sum += v[i].x + v[i].y + v[i].z + v[i].w;
        sq  += v[i].x * v[i].x + v[i].y * v[i].y + v[i].z * v[i].z + v[i].w * v[i].w;
    }
#pragma unroll
    for (int o = 16; o; o >>= 1) {
        sum += __shfl_xor_sync(0xffffffffu, sum, o);
        sq  += __shfl_xor_sync(0xffffffffu, sq,  o);
    }
    const float mu  = sum * (1.f / 512.f);
    const float var = fmaxf(sq * (1.f / 512.f) - mu * mu, 0.f);
    const float inv = 1.f / (sqrtf(var) + 1e-9f);

    const float4* g4 = reinterpret_cast<const float4*>(gain);
    const float4* b4 = reinterpret_cast<const float4*>(bias);
#pragma unroll
    for (int i = 0; i < 4; i++) {
        int j = lane + i * 32;
        float4 g = g4[j], bb = b4[j], x = v[i], y;
        y.x = fmaxf(g.x * (x.x - mu) * inv + bb.x, 0.f);
        y.y = fmaxf(g.y * (x.y - mu) * inv + bb.y, 0.f);
        y.z = fmaxf(g.z * (x.z - mu) * inv + bb.z, 0.f);
        y.w = fmaxf(g.w * (x.w - mu) * inv + bb.w, 0.f);
        __half h0 = __float2half_rn(y.x), h1 = __float2half_rn(y.y);
        __half h2 = __float2half_rn(y.z), h3 = __float2half_rn(y.w);
        __half l0 = __float2half_rn(y.x - __half2float(h0));
        __half l1 = __float2half_rn(y.y - __half2float(h1));
        __half l2 = __float2half_rn(y.z - __half2float(h2));
        __half l3 = __float2half_rn(y.w - __half2float(h3));
        reinterpret_cast<uint2*>(YH + (size_t)row * 512)[j] =
            make_uint2(pack2h(h0, h1), pack2h(h2, h3));
        reinterpret_cast<uint2*>(YL + (size_t)row * 512)[j] =
            make_uint2(pack2h(l0, l1), pack2h(l2, l3));
    }
}

// ---------------------------------------------------------------------------
// Fused LN2 + LSTM finalize (validated bit-identical in R9/R12).
// ---------------------------------------------------------------------------
__global__ __launch_bounds__(256)
void final2_k(const float* __restrict__ X, const float* __restrict__ z,
              const float* __restrict__ c_state, const float* __restrict__ gain,
              const float* __restrict__ bias, float* __restrict__ out)
{
    const int row  = blockIdx.x * 8 + (threadIdx.x >> 5);
    const int lane = threadIdx.x & 31;
    const float4* in = reinterpret_cast<const float4*>(X + (size_t)row * 512);

    float4 v[4];
    float sum = 0.f, sq = 0.f;
#pragma unroll
    for (int i = 0; i < 4; i++) {
        v[i] = in[lane + i * 32];
        sum += v[i].x + v[i].y + v[i].z + v[i].w;
        sq  += v[i].x * v[i].x + v[i].y * v[i].y + v[i].z * v[i].z + v[i].w * v[i].w;
    }
#pragma unroll
    for (int o = 16; o; o >>= 1) {
        sum += __shfl_xor_sync(0xffffffffu, sum, o);
        sq  += __shfl_xor_sync(0xffffffffu, sq,  o);
    }
    const float mu  = sum * (1.f / 512.f);
    const float var = fmaxf(sq * (1.f / 512.f) - mu * mu, 0.f);
    const float inv = 1.f / (sqrtf(var) + 1e-9f);

    const float4* g4 = reinterpret_cast<const float4*>(gain);
    const float4* b4 = reinterpret_cast<const float4*>(bias);
    const float*  zr = z + (size_t)row * N3;
#pragma unroll
    for (int i = 0; i < 4; i++) {
        int j = lane + i * 32;
        float4 g = g4[j], bb = b4[j], x = v[i], u;
        u.x = g.x * (x.x - mu) * inv + bb.x;
        u.y = g.y * (x.y - mu) * inv + bb.y;
        u.z = g.z * (x.z - mu) * inv + bb.z;
        u.w = g.w * (x.w - mu) * inv + bb.w;

        const float4 i4 = *reinterpret_cast<const float4*>(zr + j * 4);
        const float4 f4 = *reinterpret_cast<const float4*>(zr + 512 + j * 4);
        const float4 o4 = *reinterpret_cast<const float4*>(zr + 1024 + j * 4);
        const float4 c4 = reinterpret_cast<const float4*>(c_state + (size_t)row * 512)[j];

        float4 cn, hn;
        cn.x = f4.x * c4.x + i4.x * tanhf(u.x); hn.x = o4.x * tanhf(cn.x);
        cn.y = f4.y * c4.y + i4.y * tanhf(u.y); hn.y = o4.y * tanhf(cn.y);
        cn.z = f4.z * c4.z + i4.z * tanhf(u.z); hn.z = o4.z * tanhf(cn.z);
        cn.w = f4.w * c4.w + i4.w * tanhf(u.w); hn.w = o4.w * tanhf(cn.w);

        reinterpret_cast<float4*>(out + (size_t)row * 512)[j] = hn;
        reinterpret_cast<float4*>(out + (size_t)NROWS * DDIM + (size_t)row * 512)[j] = cn;
    }
}

// ---------------------------------------------------------------------------
// Launch
// ---------------------------------------------------------------------------
extern "C" void kernel_launch(void* const* d_in, const int* in_sizes, int n_in,
                              void* d_out, int out_size)
{
    const float* inputs   = (const float*)d_in[0];
    const float* h_state  = (const float*)d_in[1];
    const float* c_state  = (const float*)d_in[2];
    const float* kernel_w = (const float*)d_in[3];
    const float* rec_w    = (const float*)d_in[4];
    const float* W_q      = (const float*)d_in[5];
    const float* W_k      = (const float*)d_in[6];
    const float* W_v      = (const float*)d_in[7];
    const float* mlp1     = (const float*)d_in[8];
    const float* mlp2     = (const float*)d_in[9];
    const float* gain1    = (const float*)d_in[10];
    const float* gain2    = (const float*)d_in[11];
    const float* bias1    = (const float*)d_in[12];
    const float* bias2    = (const float*)d_in[13];
    const float* bias     = (const float*)d_in[14];
    float* out = (float*)d_out;

    float *pQKV, *pKVx, *pMlp, *pXz, *pZ;
    cudaGetSymbolAddress((void**)&pQKV, g_QKV);
    cudaGetSymbolAddress((void**)&pKVx, g_KVx);
    cudaGetSymbolAddress((void**)&pMlp, g_mlp);
    cudaGetSymbolAddress((void**)&pXz,  g_xz);
    cudaGetSymbolAddress((void**)&pZ,   g_z);

    __half *csh,*csl,*hsh,*inh,*inl,*atth,*attl,*lnh,*lnl;
    cudaGetSymbolAddress((void**)&csh,  g_cs_h);  cudaGetSymbolAddress((void**)&csl,  g_cs_l);
    cudaGetSymbolAddress((void**)&hsh,  g_hs_h);
    cudaGetSymbolAddress((void**)&inh,  g_in_h);  cudaGetSymbolAddress((void**)&inl,  g_in_l);
    cudaGetSymbolAddress((void**)&atth, g_att_h); cudaGetSymbolAddress((void**)&attl, g_att_l);
    cudaGetSymbolAddress((void**)&lnh,  g_ln_h);  cudaGetSymbolAddress((void**)&lnl,  g_ln_l);

    __half *wqkvh,*wqkvl,*m1h,*m1l,*m2h,*m2l,*krh,*rkh;
    cudaGetSymbolAddress((void**)&wqkvh, g_wqkv_h); cudaGetSymbolAddress((void**)&wqkvl, g_wqkv_l);
    cudaGetSymbolAddress((void**)&m1h, g_m1_h); cudaGetSymbolAddress((void**)&m1l, g_m1_l);
    cudaGetSymbolAddress((void**)&m2h, g_m2_h); cudaGetSymbolAddress((void**)&m2l, g_m2_l);
    cudaGetSymbolAddress((void**)&krh, g_kr_h);
    cudaGetSymbolAddress((void**)&rkh, g_rk_h);

    cudaFuncSetAttribute(attn_k, cudaFuncAttributeMaxDynamicSharedMemorySize, 103488);
    cudaFuncSetAttribute(tc_gemm<3,0>, cudaFuncAttributeMaxDynamicSharedMemorySize, GEMM_SMEM);
    cudaFuncSetAttribute(tc_gemm<2,0>, cudaFuncAttributeMaxDynamicSharedMemorySize, GEMM_SMEM);
    cudaFuncSetAttribute(tc_gemm<1,0>, cudaFuncAttributeMaxDynamicSharedMemorySize, GEMM_SMEM);
    cudaFuncSetAttribute(tc_gemm<1,1>, cudaFuncAttributeMaxDynamicSharedMemorySize, GEMM_SMEM);

    const dim3 thr(256);

    // 0: mega prep (weights + all activation splits in one launch)
    prep_split_all<<<MEGA_BLKS, thr>>>(
        W_q, W_k, W_v, mlp1, mlp2, kernel_w, rec_w,
        wqkvh, wqkvl, m1h, m1l, m2h, m2l, krh, rkh,
        c_state, csh, csl, h_state, hsh, inputs, inh, inl);

    // 1: fused Q|K|V (3-term)
    tc_gemm<3,0><<<dim3(N3 / TN, NROWS / TM), thr, GEMM_SMEM>>>(
        csh, csl, wqkvh, wqkvl, pQKV, N3, nullptr, nullptr);

    // 2: Kx|Vx (3-term)
    tc_gemm<3,0><<<dim3(1024 / TN, BATCH / TM), thr, GEMM_SMEM>>>(
        inh, inl, wqkvh + 512 * 512, wqkvl + 512 * 512, pKVx, 1024, nullptr, nullptr);

    // 3: attention (512 threads) — now in the ncu capture slot
    attn_k<<<BATCH, 512, 103488>>>(pQKV, pKVx, atth, attl);

    // 4-6: MLP (2-term) + LN1
    tc_gemm<2,0><<<dim3(512 / TN, NROWS / TM), thr, GEMM_SMEM>>>(
        atth, attl, m1h, m1l, pMlp, 512, nullptr, nullptr);
    ln1_k<<<NROWS / 8, thr>>>(pMlp, lnh, lnl, gain1, bias1);
    tc_gemm<2,0><<<dim3(512 / TN, NROWS / TM), thr, GEMM_SMEM>>>(
        lnh, lnl, m2h, m2l, pMlp, 512, nullptr, nullptr);

    // 7-8: gates (1-term): xz, then z = sigmoid(hz + xz + bias)
    tc_gemm<1,0><<<dim3(N3 / TN, BATCH / TM), thr, GEMM_SMEM>>>(
        inh, nullptr, krh, nullptr, pXz, N3, nullptr, nullptr);
    tc_gemm<1,1><<<dim3(N3 / TN, NROWS / TM), thr, GEMM_SMEM>>>(
        hsh, nullptr, rkh, nullptr, pZ, N3, pXz, bias);

    // 9: fused LN2 + finalize -> [h_new | c_new]
    final2_k<<<NROWS / 8, thr>>>(pMlp, pZ, c_state, gain2, bias2, out);
}

// round 17
// speedup vs baseline: 1.0264x; 1.0264x over previous
#include <cuda_runtime.h>
#include <cuda_fp16.h>
#include <math.h>
#include <stdint.h>

// Problem constants
#define BATCH 4096
#define DDIM  512
#define SLOTS 16
#define NROWS (BATCH * SLOTS)   // 65536
#define N3    (3 * DDIM)        // 1536

// ---------------------------------------------------------------------------
// Scratch buffers (device globals — no allocations allowed)
// ---------------------------------------------------------------------------
__device__ float g_QKV [(size_t)NROWS * N3];     // Q|K|V fp32
__device__ float g_KVx [(size_t)BATCH * 1024];   // Kx|Vx fp32
__device__ float g_mlp [(size_t)NROWS * DDIM];   // mlp1 out, then mlp2 out
__device__ float g_xz  [(size_t)BATCH * N3];
__device__ float g_z   [(size_t)NROWS * N3];     // sigmoid(z) from MODE-1 GEMM

// fp16 hi/lo split activations
__device__ __half g_cs_h [(size_t)NROWS * DDIM], g_cs_l [(size_t)NROWS * DDIM];
__device__ __half g_hs_h [(size_t)NROWS * DDIM];
__device__ __half g_in_h [(size_t)BATCH * DDIM], g_in_l [(size_t)BATCH * DDIM];
__device__ __half g_att_h[(size_t)NROWS * DDIM], g_att_l[(size_t)NROWS * DDIM];
__device__ __half g_ln_h [(size_t)NROWS * DDIM], g_ln_l [(size_t)NROWS * DDIM];

// Transposed + split weights: [N][K=512] fp16 hi/lo
__device__ __half g_wqkv_h[N3 * DDIM],  g_wqkv_l[N3 * DDIM];  // rows: Q|K|V
__device__ __half g_m1_h[DDIM * DDIM],  g_m1_l[DDIM * DDIM];
__device__ __half g_m2_h[DDIM * DDIM],  g_m2_l[DDIM * DDIM];
__device__ __half g_kr_h[DDIM * N3];    // gates hi only
__device__ __half g_rk_h[DDIM * N3];

// ---------------------------------------------------------------------------
// Helpers
// ---------------------------------------------------------------------------
__device__ __forceinline__ uint32_t smem_u32(const void* p) {
    uint32_t a;
    asm("{ .reg .u64 t; cvta.to.shared.u64 t, %1; cvt.u32.u64 %0, t; }"
        : "=r"(a) : "l"(p));
    return a;
}
__device__ __forceinline__ uint32_t pack2h(__half a, __half b) {
    return (uint32_t)__half_as_ushort(a) |
           ((uint32_t)__half_as_ushort(b) << 16);
}

#define CP16(dst, src) \
    asm volatile("cp.async.ca.shared.global [%0], [%1], 16;" \
                 :: "r"(dst), "l"(src) : "memory")
#define CP_COMMIT()  asm volatile("cp.async.commit_group;" ::: "memory")
#define CP_WAIT0()   asm volatile("cp.async.wait_group 0;" ::: "memory")

#define LDSM4(r0, r1, r2, r3, addr) \
    asm volatile("ldmatrix.sync.aligned.m8n8.x4.shared.b16 {%0,%1,%2,%3}, [%4];" \
                 : "=r"(r0), "=r"(r1), "=r"(r2), "=r"(r3) : "r"(addr))

#define MMA_F16(ac, a0, a1, a2, a3, b0, b1) \
    asm volatile("mma.sync.aligned.m16n8k16.row.col.f32.f16.f16.f32 " \
                 "{%0,%1,%2,%3},{%4,%5,%6,%7},{%8,%9},{%0,%1,%2,%3};" \
                 : "+f"((ac)[0]), "+f"((ac)[1]), "+f"((ac)[2]), "+f"((ac)[3]) \
                 : "r"(a0), "r"(a1), "r"(a2), "r"(a3), "r"(b0), "r"(b1))

// ---------------------------------------------------------------------------
// Weight prep (single launch): all 7 weights -> transposed fp16 hi/lo.
// ---------------------------------------------------------------------------
__global__ __launch_bounds__(256)
void prep_all(const float* __restrict__ Wq, const float* __restrict__ Wk,
              const float* __restrict__ Wv, const float* __restrict__ M1,
              const float* __restrict__ M2, const float* __restrict__ Kr,
              const float* __restrict__ Rk,
              __half* __restrict__ wqkvh, __half* __restrict__ wqkvl,
              __half* __restrict__ m1h, __half* __restrict__ m1l,
              __half* __restrict__ m2h, __half* __restrict__ m2l,
              __half* __restrict__ krh, __half* __restrict__ rkh)
{
    const int blk = blockIdx.x;
    if (blk < 5120) {
        int seg = blk >> 10;
        int idx = ((blk & 1023) << 8) + threadIdx.x;
        const float* W; __half* Wh; __half* Wl;
        switch (seg) {
            case 0: W = Wq; Wh = wqkvh;              Wl = wqkvl;              break;
            case 1: W = Wk; Wh = wqkvh + 512 * 512;  Wl = wqkvl + 512 * 512;  break;
            case 2: W = Wv; Wh = wqkvh + 1024 * 512; Wl = wqkvl + 1024 * 512; break;
            case 3: W = M1; Wh = m1h; Wl = m1l; break;
            default:W = M2; Wh = m2h; Wl = m2l; break;
        }
        int k = idx >> 9, n = idx & 511;
        float x = W[idx];
        __half h = __float2half_rn(x);
        Wh[(size_t)n * 512 + k] = h;
        Wl[(size_t)n * 512 + k] = __float2half_rn(x - __half2float(h));
    } else {
        const float* W; __half* Wh; int idx;
        if (blk < 8192) { idx = ((blk - 5120) << 8) + threadIdx.x; W = Kr; Wh = krh; }
        else            { idx = ((blk - 8192) << 8) + threadIdx.x; W = Rk; Wh = rkh; }
        int k = idx / N3, n = idx - k * N3;
        Wh[(size_t)n * 512 + k] = __float2half_rn(W[idx]);
    }
}

// ---------------------------------------------------------------------------
// Activation split: X fp32 -> H/L fp16 (LO==false: hi only)
// ---------------------------------------------------------------------------
template <bool LO>
__global__ __launch_bounds__(256)
void split_k(const float* __restrict__ X, __half* __restrict__ H,
             __half* __restrict__ L)
{
    size_t idx = (size_t)blockIdx.x * 256 + threadIdx.x;
    float4 x = reinterpret_cast<const float4*>(X)[idx];
    __half h0 = __float2half_rn(x.x), h1 = __float2half_rn(x.y);
    __half h2 = __float2half_rn(x.z), h3 = __float2half_rn(x.w);
    reinterpret_cast<uint2*>(H)[idx] = make_uint2(pack2h(h0, h1), pack2h(h2, h3));
    if (LO) {
        __half l0 = __float2half_rn(x.x - __half2float(h0));
        __half l1 = __float2half_rn(x.y - __half2float(h1));
        __half l2 = __float2half_rn(x.z - __half2float(h2));
        __half l3 = __float2half_rn(x.w - __half2float(h3));
        reinterpret_cast<uint2*>(L)[idx] = make_uint2(pack2h(l0, l1), pack2h(l2, l3));
    }
}

// ---------------------------------------------------------------------------
// mma.sync fp16-split GEMM: C(M,N) = A(M,512) @ W(512,N)
// NT terms: 3 = AhBh+AlBh+AhBl (QKV), 2 = AhBh+AlBh (mlp), 1 = AhBh (gates).
// CTA 128x128, BK=32, 8 warps, warp tile 64x32, 2-stage cp.async pipeline,
// 2 CTAs/SM. MODE 0: plain store. MODE 1: sigmoid(acc + xz + bias).
// ---------------------------------------------------------------------------
#define TM 128
#define TN 128
#define TK 32
#define NCH 16
#define RSB 80
#define OFF_AH 0
#define OFF_AL (128 * RSB)
#define OFF_BH (256 * RSB)
#define OFF_BL (384 * RSB)
#define STAGE_B (512 * RSB)       // 40960
#define GEMM_SMEM (2 * STAGE_B)   // 81920 -> 2 CTAs/SM

template <int NT, int MODE>
__global__ __launch_bounds__(256, 2)
void tc_gemm(const __half* __restrict__ Ah, const __half* __restrict__ Al,
             const __half* __restrict__ Bh, const __half* __restrict__ Bl,
             float* __restrict__ C, int N,
             const float* __restrict__ xz, const float* __restrict__ bias)
{
    extern __shared__ char smem[];
    const uint32_t tb = smem_u32(smem);

    const int t    = threadIdx.x;
    const int w    = t >> 5;
    const int lane = t & 31;
    const int wmBase = (w >> 2) * 64;
    const int wnBase = (w & 3) * 32;
    const int rowBase = blockIdx.y * TM;
    const int nBase   = blockIdx.x * TN;

    const uint32_t aRow = (uint32_t)(lane & 15);
    const uint32_t aK   = (uint32_t)((lane >> 4) * 8);
    const uint32_t bRow = (uint32_t)((lane & 7) + ((lane >> 4) << 3));
    const uint32_t bK   = (uint32_t)(((lane >> 3) & 1) * 8);

    float acc[4][4][4];
#pragma unroll
    for (int i = 0; i < 4; i++)
#pragma unroll
        for (int j = 0; j < 4; j++)
#pragma unroll
            for (int q = 0; q < 4; q++) acc[i][j][q] = 0.f;

    auto issue = [&](int c, int s) {
        const uint32_t st = tb + s * STAGE_B;
        const int kb = c * TK;
#pragma unroll
        for (int i = 0; i < 2; i++) {
            int v = i * 256 + t;
            int row = v >> 2, seg = v & 3;
            const size_t so = (size_t)(rowBase + row) * 512 + kb + seg * 8;
            uint32_t doff = (uint32_t)(row * RSB + seg * 16);
            CP16(st + OFF_AH + doff, Ah + so);
            if (NT >= 2) CP16(st + OFF_AL + doff, Al + so);
        }
#pragma unroll
        for (int i = 0; i < 2; i++) {
            int v = i * 256 + t;
            int row = v >> 2, seg = v & 3;
            const size_t so = (size_t)(nBase + row) * 512 + kb + seg * 8;
            uint32_t doff = (uint32_t)(row * RSB + seg * 16);
            CP16(st + OFF_BH + doff, Bh + so);
            if (NT == 3) CP16(st + OFF_BL + doff, Bl + so);
        }
        CP_COMMIT();
    };

    auto compute = [&](int s) {
        const uint32_t sAh = tb + s * STAGE_B + OFF_AH;
        const uint32_t sAl = tb + s * STAGE_B + OFF_AL;
        const uint32_t sBh = tb + s * STAGE_B + OFF_BH;
        const uint32_t sBl = tb + s * STAGE_B + OFF_BL;
#pragma unroll
        for (int kk = 0; kk < TK; kk += 16) {
            uint32_t bh[2][4], bl[2][4];
#pragma unroll
            for (int p = 0; p < 2; p++) {
                uint32_t addr = (uint32_t)((wnBase + p * 16 + bRow) * RSB + (kk + bK) * 2);
                LDSM4(bh[p][0], bh[p][1], bh[p][2], bh[p][3], sBh + addr);
                if (NT == 3) LDSM4(bl[p][0], bl[p][1], bl[p][2], bl[p][3], sBl + addr);
            }
#pragma unroll
            for (int mi = 0; mi < 4; mi++) {
                uint32_t addr = (uint32_t)((wmBase + mi * 16 + aRow) * RSB + (kk + aK) * 2);
                uint32_t ah0, ah1, ah2, ah3, al0, al1, al2, al3;
                LDSM4(ah0, ah1, ah2, ah3, sAh + addr);
                if (NT >= 2) LDSM4(al0, al1, al2, al3, sAl + addr);
#pragma unroll
                for (int g = 0; g < 4; g++) {
                    int p = g >> 1, q = (g & 1) * 2;
                    MMA_F16(acc[mi][g], ah0, ah1, ah2, ah3, bh[p][q], bh[p][q + 1]);
                    if (NT >= 2)
                        MMA_F16(acc[mi][g], al0, al1, al2, al3, bh[p][q], bh[p][q + 1]);
                    if (NT == 3)
                        MMA_F16(acc[mi][g], ah0, ah1, ah2, ah3, bl[p][q], bl[p][q + 1]);
                }
            }
        }
    };

    issue(0, 0);
    for (int c = 0; c < NCH; c++) {
        const int s = c & 1;
        CP_WAIT0();
        __syncthreads();
        if (c + 1 < NCH) issue(c + 1, s ^ 1);
        compute(s);
    }

    const int tr  = lane >> 2;
    const int tc2 = (lane & 3) * 2;
#pragma unroll
    for (int mi = 0; mi < 4; mi++) {
#pragma unroll
        for (int g = 0; g < 4; g++) {
            int row = rowBase + wmBase + mi * 16 + tr;
            int col = nBase + wnBase + g * 8 + tc2;
            float v0 = acc[mi][g][0], v1 = acc[mi][g][1];
            float v2 = acc[mi][g][2], v3 = acc[mi][g][3];
            if (MODE == 1) {
                const float* xr0 = xz + (size_t)(row >> 4) * N3 + col;
                const float* xr1 = xz + (size_t)((row + 8) >> 4) * N3 + col;
                float b0 = bias[col], b1 = bias[col + 1];
                v0 = 1.f / (1.f + expf(-(v0 + xr0[0] + b0)));
                v1 = 1.f / (1.f + expf(-(v1 + xr0[1] + b1)));
                v2 = 1.f / (1.f + expf(-(v2 + xr1[0] + b0)));
                v3 = 1.f / (1.f + expf(-(v3 + xr1[1] + b1)));
            }
            *reinterpret_cast<float2*>(C + (size_t)row * N + col)       = make_float2(v0, v1);
            *reinterpret_cast<float2*>(C + (size_t)(row + 8) * N + col) = make_float2(v2, v3);
        }
    }
}

// ---------------------------------------------------------------------------
// Attention: TWO CTAs per batch (each owns 8 of the 16 Q rows), 512 threads,
// 2 CTAs/SM (86.6 KB smem, <=64 regs). K/V staged per CTA; same reduction
// orders as before -> bit-identical output.
// ---------------------------------------------------------------------------
#define ATTN_SMEM ((8704 + 8704 + 4096 + 160) * 4)   // sK+sV+sQ+sS = 86656

__global__ __launch_bounds__(512, 2)
void attn_k(const float* __restrict__ QKV, const float* __restrict__ KVx,
            __half* __restrict__ AttH, __half* __restrict__ AttL)
{
    extern __shared__ float sm[];
    float* sK = sm;                  // 17*512
    float* sV = sK + 8704;           // 17*512
    float* sQ = sV + 8704;           // 8*512
    float* sS = sQ + 4096;           // 8*17 (+pad)

    const int b = blockIdx.y;
    const int h = blockIdx.x;        // Q-row half: rows h*8 .. h*8+7
    const int t = threadIdx.x;
    const size_t base3 = (size_t)b * SLOTS * N3;

    // K/V: 2048 float4 each
    for (int i = t; i < 2048; i += 512) {
        int j = i >> 7, d4 = i & 127;
        const float4* row = reinterpret_cast<const float4*>(QKV + base3 + (size_t)j * N3);
        reinterpret_cast<float4*>(sK)[i] = row[128 + d4];
        reinterpret_cast<float4*>(sV)[i] = row[256 + d4];
    }
    for (int i = t; i < 128; i += 512) {
        const float4* kx = reinterpret_cast<const float4*>(KVx + (size_t)b * 1024);
        reinterpret_cast<float4*>(sK + 8192)[i] = kx[i];
        reinterpret_cast<float4*>(sV + 8192)[i] = kx[128 + i];
    }
    // Q half: 1024 float4
    for (int i = t; i < 1024; i += 512) {
        int j = i >> 7, d4 = i & 127;
        const float4* row = reinterpret_cast<const float4*>(
            QKV + base3 + (size_t)(h * 8 + j) * N3);
        reinterpret_cast<float4*>(sQ)[i] = row[d4];
    }
    __syncthreads();

    // 136 dots of length 512; 16 warps
    const int w = t >> 5, lane = t & 31;
    for (int p = w; p < 136; p += 16) {
        int j = p / 17, l = p - j * 17;
        const float* q = sQ + j * 512;
        const float* k = sK + l * 512;
        float s = 0.f;
        for (int d = lane; d < 512; d += 32) s += q[d] * k[d];
#pragma unroll
        for (int o = 16; o; o >>= 1) s += __shfl_xor_sync(0xffffffffu, s, o);
        if (lane == 0) sS[p] = s * 22.627416997969522f;
    }
    __syncthreads();

    if (t < 8) {
        float m = -INFINITY;
        for (int l = 0; l < 17; l++) m = fmaxf(m, sS[t * 17 + l]);
        float sum = 0.f;
        for (int l = 0; l < 17; l++) {
            float e = expf(sS[t * 17 + l] - m);
            sS[t * 17 + l] = e;
            sum += e;
        }
        float inv = 1.f / sum;
        for (int l = 0; l < 17; l++) sS[t * 17 + l] *= inv;
    }
    __syncthreads();

    // AV: thread owns column d = t; 8 independent accumulators
    float acc[8];
#pragma unroll
    for (int j = 0; j < 8; j++) acc[j] = 0.f;
#pragma unroll
    for (int l = 0; l < 17; l++) {
        float v = sV[l * 512 + t];
#pragma unroll
        for (int j = 0; j < 8; j++) acc[j] += sS[j * 17 + l] * v;
    }
    const size_t obase = (size_t)b * 8192 + (size_t)h * 8 * 512;
#pragma unroll
    for (int j = 0; j < 8; j++) {
        __half hh = __float2half_rn(acc[j]);
        AttH[obase + j * 512 + t] = hh;
        AttL[obase + j * 512 + t] = __float2half_rn(acc[j] - __half2float(hh));
    }
}

// ---------------------------------------------------------------------------
// LN1 (relu + fp16 hi/lo split output)
// ---------------------------------------------------------------------------
__global__ __launch_bounds__(256)
void ln1_k(const float* __restrict__ X, __half* __restrict__ YH,
           __half* __restrict__ YL, const float* __restrict__ gain,
           const float* __restrict__ bias)
{
    const int row  = blockIdx.x * 8 + (threadIdx.x >> 5);
    const int lane = threadIdx.x & 31;
    const float4* in = reinterpret_cast<const float4*>(X + (size_t)row * 512);

    float4 v[4];
    float sum = 0.f, sq = 0.f;
#pragma unroll
    for (int i = 0; i < 4; i++) {
        v[i] = in[lane + i * 32];
        sum += v[i].x + v[i].y + v[i].z + v[i].w;
        sq  += v[i].x * v[i].x + v[i].y * v[i].y + v[i].z * v[i].z + v[i].w * v[i].w;
    }
#pragma unroll
    for (int o = 16; o; o >>= 1) {
        sum += __shfl_xor_sync(0xffffffffu, sum, o);
        sq  += __shfl_xor_sync(0xffffffffu, sq,  o);
    }
    const float mu  = sum * (1.f / 512.f);
    const float var = fmaxf(sq * (1.f / 512.f) - mu * mu, 0.f);
    const float inv = 1.f / (sqrtf(var) + 1e-9f);

    const float4* g4 = reinterpret_cast<const float4*>(gain);
    const float4* b4 = reinterpret_cast<const float4*>(bias);
#pragma unroll
    for (int i = 0; i < 4; i++) {
        int j = lane + i * 32;
        float4 g = g4[j], bb = b4[j], x = v[i], y;
        y.x = fmaxf(g.x * (x.x - mu) * inv + bb.x, 0.f);
        y.y = fmaxf(g.y * (x.y - mu) * inv + bb.y, 0.f);
        y.z = fmaxf(g.z * (x.z - mu) * inv + bb.z, 0.f);
        y.w = fmaxf(g.w * (x.w - mu) * inv + bb.w, 0.f);
        __half h0 = __float2half_rn(y.x), h1 = __float2half_rn(y.y);
        __half h2 = __float2half_rn(y.z), h3 = __float2half_rn(y.w);
        __half l0 = __float2half_rn(y.x - __half2float(h0));
        __half l1 = __float2half_rn(y.y - __half2float(h1));
        __half l2 = __float2half_rn(y.z - __half2float(h2));
        __half l3 = __float2half_rn(y.w - __half2float(h3));
        reinterpret_cast<uint2*>(YH + (size_t)row * 512)[j] =
            make_uint2(pack2h(h0, h1), pack2h(h2, h3));
        reinterpret_cast<uint2*>(YL + (size_t)row * 512)[j] =
            make_uint2(pack2h(l0, l1), pack2h(l2, l3));
    }
}

// ---------------------------------------------------------------------------
// Fused LN2 + LSTM finalize (validated bit-identical in R9/R12).
// ---------------------------------------------------------------------------
__global__ __launch_bounds__(256)
void final2_k(const float* __restrict__ X, const float* __restrict__ z,
              const float* __restrict__ c_state, const float* __restrict__ gain,
              const float* __restrict__ bias, float* __restrict__ out)
{
    const int row  = blockIdx.x * 8 + (threadIdx.x >> 5);
    const int lane = threadIdx.x & 31;
    const float4* in = reinterpret_cast<const float4*>(X + (size_t)row * 512);

    float4 v[4];
    float sum = 0.f, sq = 0.f;
#pragma unroll
    for (int i = 0; i < 4; i++) {
        v[i] = in[lane + i * 32];
        sum += v[i].x + v[i].y + v[i].z + v[i].w;
        sq  += v[i].x * v[i].x + v[i].y * v[i].y + v[i].z * v[i].z + v[i].w * v[i].w;
    }
#pragma unroll
    for (int o = 16; o; o >>= 1) {
        sum += __shfl_xor_sync(0xffffffffu, sum, o);
        sq  += __shfl_xor_sync(0xffffffffu, sq,  o);
    }
    const float mu  = sum * (1.f / 512.f);
    const float var = fmaxf(sq * (1.f / 512.f) - mu * mu, 0.f);
    const float inv = 1.f / (sqrtf(var) + 1e-9f);

    const float4* g4 = reinterpret_cast<const float4*>(gain);
    const float4* b4 = reinterpret_cast<const float4*>(bias);
    const float*  zr = z + (size_t)row * N3;
#pragma unroll
    for (int i = 0; i < 4; i++) {
        int j = lane + i * 32;
        float4 g = g4[j], bb = b4[j], x = v[i], u;
        u.x = g.x * (x.x - mu) * inv + bb.x;
        u.y = g.y * (x.y - mu) * inv + bb.y;
        u.z = g.z * (x.z - mu) * inv + bb.z;
        u.w = g.w * (x.w - mu) * inv + bb.w;

        const float4 i4 = *reinterpret_cast<const float4*>(zr + j * 4);
        const float4 f4 = *reinterpret_cast<const float4*>(zr + 512 + j * 4);
        const float4 o4 = *reinterpret_cast<const float4*>(zr + 1024 + j * 4);
        const float4 c4 = reinterpret_cast<const float4*>(c_state + (size_t)row * 512)[j];

        float4 cn, hn;
        cn.x = f4.x * c4.x + i4.x * tanhf(u.x); hn.x = o4.x * tanhf(cn.x);
        cn.y = f4.y * c4.y + i4.y * tanhf(u.y); hn.y = o4.y * tanhf(cn.y);
        cn.z = f4.z * c4.z + i4.z * tanhf(u.z); hn.z = o4.z * tanhf(cn.z);
        cn.w = f4.w * c4.w + i4.w * tanhf(u.w); hn.w = o4.w * tanhf(cn.w);

        reinterpret_cast<float4*>(out + (size_t)row * 512)[j] = hn;
        reinterpret_cast<float4*>(out + (size_t)NROWS * DDIM + (size_t)row * 512)[j] = cn;
    }
}

// ---------------------------------------------------------------------------
// Launch
// ---------------------------------------------------------------------------
extern "C" void kernel_launch(void* const* d_in, const int* in_sizes, int n_in,
                              void* d_out, int out_size)
{
    const float* inputs   = (const float*)d_in[0];
    const float* h_state  = (const float*)d_in[1];
    const float* c_state  = (const float*)d_in[2];
    const float* kernel_w = (const float*)d_in[3];
    const float* rec_w    = (const float*)d_in[4];
    const float* W_q      = (const float*)d_in[5];
    const float* W_k      = (const float*)d_in[6];
    const float* W_v      = (const float*)d_in[7];
    const float* mlp1     = (const float*)d_in[8];
    const float* mlp2     = (const float*)d_in[9];
    const float* gain1    = (const float*)d_in[10];
    const float* gain2    = (const float*)d_in[11];
    const float* bias1    = (const float*)d_in[12];
    const float* bias2    = (const float*)d_in[13];
    const float* bias     = (const float*)d_in[14];
    float* out = (float*)d_out;

    float *pQKV, *pKVx, *pMlp, *pXz, *pZ;
    cudaGetSymbolAddress((void**)&pQKV, g_QKV);
    cudaGetSymbolAddress((void**)&pKVx, g_KVx);
    cudaGetSymbolAddress((void**)&pMlp, g_mlp);
    cudaGetSymbolAddress((void**)&pXz,  g_xz);
    cudaGetSymbolAddress((void**)&pZ,   g_z);

    __half *csh,*csl,*hsh,*inh,*inl,*atth,*attl,*lnh,*lnl;
    cudaGetSymbolAddress((void**)&csh,  g_cs_h);  cudaGetSymbolAddress((void**)&csl,  g_cs_l);
    cudaGetSymbolAddress((void**)&hsh,  g_hs_h);
    cudaGetSymbolAddress((void**)&inh,  g_in_h);  cudaGetSymbolAddress((void**)&inl,  g_in_l);
    cudaGetSymbolAddress((void**)&atth, g_att_h); cudaGetSymbolAddress((void**)&attl, g_att_l);
    cudaGetSymbolAddress((void**)&lnh,  g_ln_h);  cudaGetSymbolAddress((void**)&lnl,  g_ln_l);

    __half *wqkvh,*wqkvl,*m1h,*m1l,*m2h,*m2l,*krh,*rkh;
    cudaGetSymbolAddress((void**)&wqkvh, g_wqkv_h); cudaGetSymbolAddress((void**)&wqkvl, g_wqkv_l);
    cudaGetSymbolAddress((void**)&m1h, g_m1_h); cudaGetSymbolAddress((void**)&m1l, g_m1_l);
    cudaGetSymbolAddress((void**)&m2h, g_m2_h); cudaGetSymbolAddress((void**)&m2l, g_m2_l);
    cudaGetSymbolAddress((void**)&krh, g_kr_h);
    cudaGetSymbolAddress((void**)&rkh, g_rk_h);

    cudaFuncSetAttribute(attn_k, cudaFuncAttributeMaxDynamicSharedMemorySize, ATTN_SMEM);
    cudaFuncSetAttribute(tc_gemm<3,0>, cudaFuncAttributeMaxDynamicSharedMemorySize, GEMM_SMEM);
    cudaFuncSetAttribute(tc_gemm<2,0>, cudaFuncAttributeMaxDynamicSharedMemorySize, GEMM_SMEM);
    cudaFuncSetAttribute(tc_gemm<1,0>, cudaFuncAttributeMaxDynamicSharedMemorySize, GEMM_SMEM);
    cudaFuncSetAttribute(tc_gemm<1,1>, cudaFuncAttributeMaxDynamicSharedMemorySize, GEMM_SMEM);

    const dim3 thr(256);

    // 0: all weight prep
    prep_all<<<11264, thr>>>(W_q, W_k, W_v, mlp1, mlp2, kernel_w, rec_w,
                             wqkvh, wqkvl, m1h, m1l, m2h, m2l, krh, rkh);
    // 1-2: state splits
    split_k<true ><<<((size_t)NROWS * DDIM / 4) / 256, thr>>>(c_state, csh, csl);
    split_k<false><<<((size_t)NROWS * DDIM / 4) / 256, thr>>>(h_state, hsh, nullptr);

    // 3: fused Q|K|V (3-term)
    tc_gemm<3,0><<<dim3(N3 / TN, NROWS / TM), thr, GEMM_SMEM>>>(
        csh, csl, wqkvh, wqkvl, pQKV, N3, nullptr, nullptr);

    // 4: input split, 5: Kx|Vx (3-term)
    split_k<true><<<((size_t)BATCH * DDIM / 4) / 256, thr>>>(inputs, inh, inl);
    tc_gemm<3,0><<<dim3(1024 / TN, BATCH / TM), thr, GEMM_SMEM>>>(
        inh, inl, wqkvh + 512 * 512, wqkvl + 512 * 512, pKVx, 1024, nullptr, nullptr);

    // 6: attention — 2 CTAs per batch, 2 CTAs/SM
    attn_k<<<dim3(2, BATCH), 512, ATTN_SMEM>>>(pQKV, pKVx, atth, attl);

    // 7-9: MLP (2-term) + LN1
    tc_gemm<2,0><<<dim3(512 / TN, NROWS / TM), thr, GEMM_SMEM>>>(
        atth, attl, m1h, m1l, pMlp, 512, nullptr, nullptr);
    ln1_k<<<NROWS / 8, thr>>>(pMlp, lnh, lnl, gain1, bias1);
    tc_gemm<2,0><<<dim3(512 / TN, NROWS / TM), thr, GEMM_SMEM>>>(
        lnh, lnl, m2h, m2l, pMlp, 512, nullptr, nullptr);

    // 10-11: gates (1-term): xz, then z = sigmoid(hz + xz + bias)
    tc_gemm<1,0><<<dim3(N3 / TN, BATCH / TM), thr, GEMM_SMEM>>>(
        inh, nullptr, krh, nullptr, pXz, N3, nullptr, nullptr);
    tc_gemm<1,1><<<dim3(N3 / TN, NROWS / TM), thr, GEMM_SMEM>>>(
        hsh, nullptr, rkh, nullptr, pZ, N3, pXz, bias);

    // 12: fused LN2 + finalize -> [h_new | c_new]
    final2_k<<<NROWS / 8, thr>>>(pMlp, pZ, c_state, gain2, bias2, out);
}